// round 16
// baseline (speedup 1.0000x reference)
#include <cuda_runtime.h>

typedef unsigned long long u64;

#define B_    1024
#define C_    200
#define HW_   225
#define F_    12
#define FR_   6
#define NELEM (C_*HW_)   /* 45000 */
#define BT    4          /* batches per K1 block */
#define CCH   8          /* channels per staged chunk */
#define NCHK  (C_/CCH)   /* 25 chunks */

// ---------------- scratch (static device arrays; no allocation) -------------
__device__ float  g_pp  [B_*C_];    // p[b][c] - mean_c(p[b])
__device__ float2 g_an  [B_*HW_];   // {a*rs, rs} per (b,n)
__device__ float4 g_ctab[C_];       // {ln_g, (d-md)*ln_g, ln_b, 0}

// ---------------- packed-f32 helpers ---------------------------------------
__device__ __forceinline__ u64 pk2(float lo, float hi){
    u64 r; asm("mov.b64 %0, {%1,%2};" : "=l"(r) : "f"(lo), "f"(hi)); return r;
}
__device__ __forceinline__ void upk2(u64 v, float &lo, float &hi){
    asm("mov.b64 {%0,%1}, %2;" : "=f"(lo), "=f"(hi) : "l"(v));
}
__device__ __forceinline__ u64 fma2(u64 a, u64 b, u64 c){
    u64 d; asm("fma.rn.f32x2 %0, %1, %2, %3;" : "=l"(d) : "l"(a), "l"(b), "l"(c));
    return d;
}

// ---------------- mbarrier / TMA-bulk helpers -------------------------------
__device__ __forceinline__ void mbar_init(unsigned a, unsigned cnt){
    asm volatile("mbarrier.init.shared.b64 [%0], %1;" :: "r"(a), "r"(cnt) : "memory");
}
__device__ __forceinline__ void mbar_arrive(unsigned a){
    asm volatile("mbarrier.arrive.shared.b64 _, [%0];" :: "r"(a) : "memory");
}
__device__ __forceinline__ void mbar_expect_tx(unsigned a, unsigned tx){
    asm volatile("mbarrier.arrive.expect_tx.shared.b64 _, [%0], %1;" :: "r"(a), "r"(tx) : "memory");
}
__device__ __forceinline__ void mbar_wait(unsigned a, unsigned parity){
    unsigned done;
    asm volatile(
        "{\n\t.reg .pred p;\n\t"
        "mbarrier.try_wait.parity.acquire.cta.shared::cta.b64 p, [%1], %2;\n\t"
        "selp.b32 %0, 1, 0, p;\n\t}"
        : "=r"(done) : "r"(a), "r"(parity) : "memory");
    if (!done){
        asm volatile(
            "{\n\t.reg .pred P1;\n\t"
            "WAIT_LOOP_%=:\n\t"
            "mbarrier.try_wait.parity.acquire.cta.shared::cta.b64 P1, [%0], %1, 0x989680;\n\t"
            "@P1 bra.uni WAIT_DONE_%=;\n\t"
            "bra.uni WAIT_LOOP_%=;\n\t"
            "WAIT_DONE_%=:\n\t}"
            :: "r"(a), "r"(parity) : "memory");
    }
}
__device__ __forceinline__ void tma_bulk(unsigned dst, const float* src, unsigned bytes, unsigned mbar){
    asm volatile(
        "cp.async.bulk.shared::cluster.global.mbarrier::complete_tx::bytes [%0], [%1], %2, [%3];"
        :: "r"(dst), "l"(src), "r"(bytes), "r"(mbar) : "memory");
}

// dynamic smem layout (bytes):
//   [0, 32000)        wpk  u64[200][20]   (18 used per channel)
//   [32000, 147200)   xs   float[4][7200] (4 buffers x 28800 B)
//   [32000, 76544)    v_s  float[4][12][232] overlay (post-GEMM only)
#define SM_WPK   0
#define SM_XS    32000
#define SM_VS    32000
#define SM_TOTAL 147200

// ============================================================================
// K1: 256 threads, BT=4 batches; thread owns n, acc[4][18] pairs.
// X staged by thread 0 via cp.async.bulk + mbarrier complete_tx: consumers
// wait on DATA parity, not on each other — no block barrier in the loop.
// (R14 champion config, unchanged.)
// ============================================================================
__global__ __launch_bounds__(256, 1) void k1_kernel(
    const float* __restrict__ X,
    const float* __restrict__ w11, const float* __restrict__ b11,
    const float* __restrict__ w21, const float* __restrict__ b21,
    const float* __restrict__ w31, const float* __restrict__ b31,
    const float* __restrict__ w41, const float* __restrict__ b41,
    const float* __restrict__ w42, const float* __restrict__ b42,
    const float* __restrict__ ln_g, const float* __restrict__ ln_b)
{
    extern __shared__ __align__(16) unsigned char dynsm[];
    u64*   wpk  = (u64*)(dynsm + SM_WPK);         // [200][20]
    float* xs   = (float*)(dynsm + SM_XS);        // [4][7200]
    float (*v_s)[F_][232] = (float (*)[F_][232])(dynsm + SM_VS);

    __shared__ __align__(8) u64 mbar[8];          // full[0..3], empty[4..7]
    __shared__ float kqs_s[BT][HW_];
    __shared__ float vm_s[BT][F_], vs_s[BT][F_], u_s[BT][FR_];
    __shared__ float wred[8][5];
    __shared__ float tot[5];
    __shared__ float sh_Vd;

    const int tid = threadIdx.x;
    const int b0  = blockIdx.x * BT;

    unsigned xs_b, mb_b;
    {
        unsigned a;
        asm("{ .reg .u64 t; cvta.to.shared.u64 t, %1; cvt.u32.u64 %0, t; }"
            : "=r"(a) : "l"(xs));        xs_b = a;
        asm("{ .reg .u64 t; cvta.to.shared.u64 t, %1; cvt.u32.u64 %0, t; }"
            : "=r"(a) : "l"(mbar));      mb_b = a;
    }
    auto full_b  = [&](int i){ return mb_b + (unsigned)i*8u; };
    auto empty_b = [&](int i){ return mb_b + 32u + (unsigned)i*8u; };

    // ---- init barriers ------------------------------------------------------
    if (tid == 0){
        #pragma unroll
        for (int i=0;i<4;i++){ mbar_init(full_b(i), 1); mbar_init(empty_b(i), 8); }
    }
    __syncthreads();

    // ---- producer helper: stage chunk s into buf s&3 ------------------------
    auto stage = [&](int s){
        int m = s >> 2;
        if (s >= 4) mbar_wait(empty_b(s & 3), (unsigned)((m-1) & 1));
        mbar_expect_tx(full_b(s & 3), BT*CCH*HW_*4u);          // 28800 bytes
        #pragma unroll
        for (int bt=0; bt<BT; bt++){
            const float* src = X + (size_t)(b0+bt)*NELEM + s*(CCH*HW_);
            unsigned dst = xs_b + (unsigned)((s & 3)*28800 + bt*7200);
            tma_bulk(dst, src, CCH*HW_*4u, full_b(s & 3));     // 7200 bytes
        }
    };

    if (tid == 0){ stage(0); stage(1); stage(2); }

    // ---- pack weights into smem (overlaps in-flight TMA) --------------------
    for (int idx = tid; idx < C_*18; idx += 256){
        int c = idx/18, j = idx%18;
        int role = j/6, jj = j%6;
        const float* w = (role==0) ? w11 : (role==1) ? w21 : w31;
        wpk[c*20 + j] = pk2(w[(2*jj)*C_ + c], w[(2*jj+1)*C_ + c]);
    }
    __syncthreads();     // wpk visible; no further block barriers in the loop

    // ---- GEMM main loop -----------------------------------------------------
    const int n = (tid < HW_) ? tid : (HW_-1);

    u64 acc[BT][18];
    #pragma unroll
    for (int bt=0;bt<BT;bt++)
        #pragma unroll
        for (int j=0;j<18;j++) acc[bt][j] = 0ULL;

    #pragma unroll 1
    for (int ch=0; ch<NCHK; ch++){
        mbar_wait(full_b(ch & 3), (unsigned)((ch >> 2) & 1));  // wait for DATA only

        const int    buf = ch & 3;
        const float* xb  = xs + buf*7200 + n;
        const u64*   wr  = wpk + (ch*CCH)*20;

        #pragma unroll
        for (int cc=0; cc<CCH; cc++){
            u64 xx[BT];
            #pragma unroll
            for (int bt=0;bt<BT;bt++){
                float x = xb[bt*1800 + cc*HW_];
                xx[bt] = pk2(x, x);
            }
            #pragma unroll
            for (int m=0;m<9;m++){
                ulonglong2 w2 = *reinterpret_cast<const ulonglong2*>(wr + cc*20 + 2*m);
                #pragma unroll
                for (int bt=0;bt<BT;bt++){
                    acc[bt][2*m]   = fma2(w2.x, xx[bt], acc[bt][2*m]);
                    acc[bt][2*m+1] = fma2(w2.y, xx[bt], acc[bt][2*m+1]);
                }
            }
        }

        if ((tid & 31) == 0) mbar_arrive(empty_b(buf));        // warp done with buf
        if (tid == 0 && ch+3 < NCHK) stage(ch+3);
    }
    __syncthreads();     // all reads of xs complete before v_s overlays it

    // ---- epilogue: biases, kqs, store v ------------------------------------
    if (tid < HW_){
        #pragma unroll
        for (int bt=0;bt<BT;bt++){
            float kv[12], qv[12], vv[12];
            #pragma unroll
            for (int j=0;j<6;j++){
                upk2(acc[bt][j],    kv[2*j], kv[2*j+1]);
                upk2(acc[bt][6+j],  qv[2*j], qv[2*j+1]);
                upk2(acc[bt][12+j], vv[2*j], vv[2*j+1]);
            }
            float kqs = 0.f;
            #pragma unroll
            for (int f=0; f<12; f++){
                float kf = kv[f] + b11[f];
                float qf = qv[f] + b21[f];
                kqs = fmaf(kf, qf, kqs);
                v_s[bt][f][n] = vv[f] + b31[f];
            }
            kqs_s[bt][n] = kqs;
        }
    }
    __syncthreads();

    // ---- vm: scrambled-reshape mean (matches reference raw reshape) --------
    if (tid < BT*F_){
        int bt = tid / F_, j = tid % F_;
        float s = 0.f;
        for (int m=0;m<HW_;m++){
            int flat = j*HW_ + m;
            int fc   = flat % 12;
            int r180 = flat % 180;
            int nn   = (flat/180)*15 + (r180/12);
            s += v_s[bt][fc][nn];
        }
        vm_s[bt][j] = s * (1.0f/HW_);
    }
    __syncthreads();

    // ---- softmax over f=12, one thread per batch ---------------------------
    if (tid < BT){
        int bt = tid;
        float mx = vm_s[bt][0];
        #pragma unroll
        for (int j=1;j<12;j++) mx = fmaxf(mx, vm_s[bt][j]);
        float e[12], ssum = 0.f;
        #pragma unroll
        for (int j=0;j<12;j++){ e[j] = __expf(vm_s[bt][j]-mx); ssum += e[j]; }
        float inv = 1.0f/ssum;
        #pragma unroll
        for (int j=0;j<12;j++) vs_s[bt][j] = e[j]*inv;
    }
    __syncthreads();

    // ---- u[bt][i] = sum_l vs[bt][l] * w41[i,l] -----------------------------
    if (tid < BT*FR_){
        int bt = tid / FR_, i = tid % FR_;
        float u = 0.f;
        #pragma unroll
        for (int l=0;l<12;l++) u = fmaf(vs_s[bt][l], w41[i*12+l], u);
        u_s[bt][i] = u;
    }
    __syncthreads();

    // ---- per-batch: p[c], d[c], reductions, then g_pp / g_an ---------------
    float Vd = 0.f;
    for (int bt=0;bt<BT;bt++){
        float p = 0.f, d = 0.f;
        if (tid < C_){
            #pragma unroll
            for (int i=0;i<6;i++){
                float wv = w42[tid*6+i];
                p = fmaf(u_s[bt][i], wv, p);
                d = fmaf(b41[i],     wv, d);
            }
            d += b42[tid];
        }
        float s0 = p, s1 = p*p, s2 = p*d, s3 = d, s4 = d*d;
        #pragma unroll
        for (int o=16;o>0;o>>=1){
            s0 += __shfl_down_sync(0xffffffffu, s0, o);
            s1 += __shfl_down_sync(0xffffffffu, s1, o);
            s2 += __shfl_down_sync(0xffffffffu, s2, o);
            s3 += __shfl_down_sync(0xffffffffu, s3, o);
            s4 += __shfl_down_sync(0xffffffffu, s4, o);
        }
        int wid = tid >> 5;
        if ((tid & 31) == 0){
            wred[wid][0]=s0; wred[wid][1]=s1; wred[wid][2]=s2; wred[wid][3]=s3; wred[wid][4]=s4;
        }
        __syncthreads();
        if (tid == 0){
            float t0=0,t1=0,t2=0,t3=0,t4=0;
            #pragma unroll
            for (int w=0;w<8;w++){ t0+=wred[w][0]; t1+=wred[w][1]; t2+=wred[w][2]; t3+=wred[w][3]; t4+=wred[w][4]; }
            tot[0]=t0; tot[1]=t1; tot[2]=t2; tot[3]=t3; tot[4]=t4;
            if (bt == 0){
                float mdd = t3*(1.0f/C_);
                sh_Vd = t4*(1.0f/C_) - mdd*mdd;
            }
        }
        __syncthreads();
        if (bt == 0) Vd = sh_Vd;
        float mp  = tot[0]*(1.0f/C_);
        float md  = tot[3]*(1.0f/C_);
        float Vp  = tot[1]*(1.0f/C_) - mp*mp;
        float Cpd = tot[2]*(1.0f/C_) - mp*md;
        if (tid < C_){
            g_pp[(b0+bt)*C_ + tid] = p - mp;
            if (bt == 0 && blockIdx.x == 0){
                float g = ln_g[tid];
                g_ctab[tid] = make_float4(g, (d - md)*g, ln_b[tid], 0.f);
            }
        }
        if (tid < HW_){
            float a   = kqs_s[bt][tid];
            float var = fmaf(a, fmaf(a, Vp, 2.0f*Cpd), Vd) + 1e-5f;
            float rs  = rsqrtf(var);
            g_an[(b0+bt)*HW_ + tid] = make_float2(a*rs, rs);
        }
        __syncthreads();
    }
}

// ============================================================================
// K2: 2048 blocks = (batch) x (c-half). Thread-per-n, groups of 10 channels.
// Gate via single-MUFU tanh: sigmoid(t) = 0.5 + 0.5*tanh(t/2).
// ============================================================================
__global__ __launch_bounds__(256, 8) void k2_kernel(
    const float* __restrict__ X, float* __restrict__ out)
{
    __shared__ float4 cdat[100];         // {pp*g, (d-md)*g, ln_b, 0}

    const int tid = threadIdx.x;
    const int b   = blockIdx.x >> 1;
    const int c0  = (blockIdx.x & 1) * 100;

    if (tid < 100){
        int c = c0 + tid;
        float  pp = g_pp[b*C_ + c];
        float4 ct = g_ctab[c];
        cdat[tid] = make_float4(pp*ct.x, ct.y, ct.z, 0.f);
    }
    __syncthreads();

    if (tid < HW_){
        float2 an = g_an[b*HW_ + tid];
        const float* xp = X   + (size_t)b*NELEM + c0*HW_ + tid;
        float*       op = out + (size_t)b*NELEM + c0*HW_ + tid;
        #pragma unroll 1
        for (int cg=0; cg<100; cg+=10){
            float xv[10];
            #pragma unroll
            for (int e=0;e<10;e++) xv[e] = xp[e*HW_];    // 10 outstanding LDGs
            #pragma unroll
            for (int e=0;e<10;e++){
                float4 cd = cdat[cg+e];
                float t = fmaf(an.x, cd.x, fmaf(an.y, cd.y, cd.z));
                t = fmaxf(t, 0.f);
                float th;
                asm("tanh.approx.f32 %0, %1;" : "=f"(th) : "f"(0.5f*t));
                // sigmoid(t) = 0.5*(1+tanh(t/2)); out = x*sigmoid
                op[e*HW_] = fmaf(xv[e]*0.5f, th, xv[e]*0.5f);
            }
            xp += 10*HW_; op += 10*HW_;
        }
    }
}

// ============================================================================
extern "C" void kernel_launch(void* const* d_in, const int* in_sizes, int n_in,
                              void* d_out, int out_size)
{
    const float* X    = (const float*)d_in[0];
    const float* w11  = (const float*)d_in[1];
    const float* b11  = (const float*)d_in[2];
    const float* w21  = (const float*)d_in[3];
    const float* b21  = (const float*)d_in[4];
    const float* w31  = (const float*)d_in[5];
    const float* b31  = (const float*)d_in[6];
    const float* w41  = (const float*)d_in[7];
    const float* b41  = (const float*)d_in[8];
    const float* w42  = (const float*)d_in[9];
    const float* b42  = (const float*)d_in[10];
    const float* ln_g = (const float*)d_in[11];
    const float* ln_b = (const float*)d_in[12];
    float* out = (float*)d_out;

    cudaFuncSetAttribute(k1_kernel, cudaFuncAttributeMaxDynamicSharedMemorySize, SM_TOTAL);

    k1_kernel<<<B_/BT, 256, SM_TOTAL>>>(X, w11,b11, w21,b21, w31,b31,
                                        w41,b41, w42,b42, ln_g, ln_b);
    k2_kernel<<<B_*2, 256>>>(X, out);
}

// round 17
// speedup vs baseline: 1.4593x; 1.4593x over previous
#include <cuda_runtime.h>

typedef unsigned long long u64;

#define B_    1024
#define C_    200
#define HW_   225
#define F_    12
#define FR_   6
#define NELEM (C_*HW_)   /* 45000 */
#define BT    4          /* batches per K1 block */
#define CCH   8          /* channels per staged chunk */
#define NCHK  (C_/CCH)   /* 25 chunks */

// ---------------- scratch (static device arrays; no allocation) -------------
__device__ float  g_pp  [B_*C_];    // p[b][c] - mean_c(p[b])
__device__ float2 g_an  [B_*HW_];   // {a*rs, rs} per (b,n)
__device__ float4 g_ctab[C_];       // {ln_g, (d-md)*ln_g, ln_b, 0}

// ---------------- packed-f32 helpers ---------------------------------------
__device__ __forceinline__ u64 pk2(float lo, float hi){
    u64 r; asm("mov.b64 %0, {%1,%2};" : "=l"(r) : "f"(lo), "f"(hi)); return r;
}
__device__ __forceinline__ void upk2(u64 v, float &lo, float &hi){
    asm("mov.b64 {%0,%1}, %2;" : "=f"(lo), "=f"(hi) : "l"(v));
}
__device__ __forceinline__ u64 fma2(u64 a, u64 b, u64 c){
    u64 d; asm("fma.rn.f32x2 %0, %1, %2, %3;" : "=l"(d) : "l"(a), "l"(b), "l"(c));
    return d;
}

// ---------------- mbarrier / TMA-bulk helpers -------------------------------
__device__ __forceinline__ void mbar_init(unsigned a, unsigned cnt){
    asm volatile("mbarrier.init.shared.b64 [%0], %1;" :: "r"(a), "r"(cnt) : "memory");
}
__device__ __forceinline__ void mbar_arrive(unsigned a){
    asm volatile("mbarrier.arrive.shared.b64 _, [%0];" :: "r"(a) : "memory");
}
__device__ __forceinline__ void mbar_expect_tx(unsigned a, unsigned tx){
    asm volatile("mbarrier.arrive.expect_tx.shared.b64 _, [%0], %1;" :: "r"(a), "r"(tx) : "memory");
}
__device__ __forceinline__ void mbar_wait(unsigned a, unsigned parity){
    unsigned done;
    asm volatile(
        "{\n\t.reg .pred p;\n\t"
        "mbarrier.try_wait.parity.acquire.cta.shared::cta.b64 p, [%1], %2;\n\t"
        "selp.b32 %0, 1, 0, p;\n\t}"
        : "=r"(done) : "r"(a), "r"(parity) : "memory");
    if (!done){
        asm volatile(
            "{\n\t.reg .pred P1;\n\t"
            "WAIT_LOOP_%=:\n\t"
            "mbarrier.try_wait.parity.acquire.cta.shared::cta.b64 P1, [%0], %1, 0x989680;\n\t"
            "@P1 bra.uni WAIT_DONE_%=;\n\t"
            "bra.uni WAIT_LOOP_%=;\n\t"
            "WAIT_DONE_%=:\n\t}"
            :: "r"(a), "r"(parity) : "memory");
    }
}
__device__ __forceinline__ void tma_bulk(unsigned dst, const float* src, unsigned bytes, unsigned mbar){
    asm volatile(
        "cp.async.bulk.shared::cluster.global.mbarrier::complete_tx::bytes [%0], [%1], %2, [%3];"
        :: "r"(dst), "l"(src), "r"(bytes), "r"(mbar) : "memory");
}

// dynamic smem layout (bytes):
//   [0, 32000)        wpk  u64[200][20]   (18 used per channel)
//   [32000, 147200)   xs   float[4][7200] (4 buffers x 28800 B)
//   [32000, 76544)    v_s  float[4][12][232] overlay (post-GEMM only)
#define SM_WPK   0
#define SM_XS    32000
#define SM_VS    32000
#define SM_TOTAL 147200

// ============================================================================
// K1: 256 threads, BT=4 batches; thread owns n, acc[4][18] pairs.
// X staged by thread 0 via cp.async.bulk + mbarrier complete_tx: consumers
// wait on DATA parity, not on each other — no block barrier in the loop.
// (R14 champion config, unchanged.)
// ============================================================================
__global__ __launch_bounds__(256, 1) void k1_kernel(
    const float* __restrict__ X,
    const float* __restrict__ w11, const float* __restrict__ b11,
    const float* __restrict__ w21, const float* __restrict__ b21,
    const float* __restrict__ w31, const float* __restrict__ b31,
    const float* __restrict__ w41, const float* __restrict__ b41,
    const float* __restrict__ w42, const float* __restrict__ b42,
    const float* __restrict__ ln_g, const float* __restrict__ ln_b)
{
    extern __shared__ __align__(16) unsigned char dynsm[];
    u64*   wpk  = (u64*)(dynsm + SM_WPK);         // [200][20]
    float* xs   = (float*)(dynsm + SM_XS);        // [4][7200]
    float (*v_s)[F_][232] = (float (*)[F_][232])(dynsm + SM_VS);

    __shared__ __align__(8) u64 mbar[8];          // full[0..3], empty[4..7]
    __shared__ float kqs_s[BT][HW_];
    __shared__ float vm_s[BT][F_], vs_s[BT][F_], u_s[BT][FR_];
    __shared__ float wred[8][5];
    __shared__ float tot[5];
    __shared__ float sh_Vd;

    const int tid = threadIdx.x;
    const int b0  = blockIdx.x * BT;

    unsigned xs_b, mb_b;
    {
        unsigned a;
        asm("{ .reg .u64 t; cvta.to.shared.u64 t, %1; cvt.u32.u64 %0, t; }"
            : "=r"(a) : "l"(xs));        xs_b = a;
        asm("{ .reg .u64 t; cvta.to.shared.u64 t, %1; cvt.u32.u64 %0, t; }"
            : "=r"(a) : "l"(mbar));      mb_b = a;
    }
    auto full_b  = [&](int i){ return mb_b + (unsigned)i*8u; };
    auto empty_b = [&](int i){ return mb_b + 32u + (unsigned)i*8u; };

    // ---- init barriers ------------------------------------------------------
    if (tid == 0){
        #pragma unroll
        for (int i=0;i<4;i++){ mbar_init(full_b(i), 1); mbar_init(empty_b(i), 8); }
    }
    __syncthreads();

    // ---- producer helper: stage chunk s into buf s&3 ------------------------
    auto stage = [&](int s){
        int m = s >> 2;
        if (s >= 4) mbar_wait(empty_b(s & 3), (unsigned)((m-1) & 1));
        mbar_expect_tx(full_b(s & 3), BT*CCH*HW_*4u);          // 28800 bytes
        #pragma unroll
        for (int bt=0; bt<BT; bt++){
            const float* src = X + (size_t)(b0+bt)*NELEM + s*(CCH*HW_);
            unsigned dst = xs_b + (unsigned)((s & 3)*28800 + bt*7200);
            tma_bulk(dst, src, CCH*HW_*4u, full_b(s & 3));     // 7200 bytes
        }
    };

    if (tid == 0){ stage(0); stage(1); stage(2); }

    // ---- pack weights into smem (overlaps in-flight TMA) --------------------
    for (int idx = tid; idx < C_*18; idx += 256){
        int c = idx/18, j = idx%18;
        int role = j/6, jj = j%6;
        const float* w = (role==0) ? w11 : (role==1) ? w21 : w31;
        wpk[c*20 + j] = pk2(w[(2*jj)*C_ + c], w[(2*jj+1)*C_ + c]);
    }
    __syncthreads();     // wpk visible; no further block barriers in the loop

    // ---- GEMM main loop -----------------------------------------------------
    const int n = (tid < HW_) ? tid : (HW_-1);

    u64 acc[BT][18];
    #pragma unroll
    for (int bt=0;bt<BT;bt++)
        #pragma unroll
        for (int j=0;j<18;j++) acc[bt][j] = 0ULL;

    #pragma unroll 1
    for (int ch=0; ch<NCHK; ch++){
        mbar_wait(full_b(ch & 3), (unsigned)((ch >> 2) & 1));  // wait for DATA only

        const int    buf = ch & 3;
        const float* xb  = xs + buf*7200 + n;
        const u64*   wr  = wpk + (ch*CCH)*20;

        #pragma unroll
        for (int cc=0; cc<CCH; cc++){
            u64 xx[BT];
            #pragma unroll
            for (int bt=0;bt<BT;bt++){
                float x = xb[bt*1800 + cc*HW_];
                xx[bt] = pk2(x, x);
            }
            #pragma unroll
            for (int m=0;m<9;m++){
                ulonglong2 w2 = *reinterpret_cast<const ulonglong2*>(wr + cc*20 + 2*m);
                #pragma unroll
                for (int bt=0;bt<BT;bt++){
                    acc[bt][2*m]   = fma2(w2.x, xx[bt], acc[bt][2*m]);
                    acc[bt][2*m+1] = fma2(w2.y, xx[bt], acc[bt][2*m+1]);
                }
            }
        }

        if ((tid & 31) == 0) mbar_arrive(empty_b(buf));        // warp done with buf
        if (tid == 0 && ch+3 < NCHK) stage(ch+3);
    }
    __syncthreads();     // all reads of xs complete before v_s overlays it

    // ---- epilogue: biases, kqs, store v ------------------------------------
    if (tid < HW_){
        #pragma unroll
        for (int bt=0;bt<BT;bt++){
            float kv[12], qv[12], vv[12];
            #pragma unroll
            for (int j=0;j<6;j++){
                upk2(acc[bt][j],    kv[2*j], kv[2*j+1]);
                upk2(acc[bt][6+j],  qv[2*j], qv[2*j+1]);
                upk2(acc[bt][12+j], vv[2*j], vv[2*j+1]);
            }
            float kqs = 0.f;
            #pragma unroll
            for (int f=0; f<12; f++){
                float kf = kv[f] + b11[f];
                float qf = qv[f] + b21[f];
                kqs = fmaf(kf, qf, kqs);
                v_s[bt][f][n] = vv[f] + b31[f];
            }
            kqs_s[bt][n] = kqs;
        }
    }
    __syncthreads();

    // ---- vm: scrambled-reshape mean (matches reference raw reshape) --------
    if (tid < BT*F_){
        int bt = tid / F_, j = tid % F_;
        float s = 0.f;
        for (int m=0;m<HW_;m++){
            int flat = j*HW_ + m;
            int fc   = flat % 12;
            int r180 = flat % 180;
            int nn   = (flat/180)*15 + (r180/12);
            s += v_s[bt][fc][nn];
        }
        vm_s[bt][j] = s * (1.0f/HW_);
    }
    __syncthreads();

    // ---- softmax over f=12, one thread per batch ---------------------------
    if (tid < BT){
        int bt = tid;
        float mx = vm_s[bt][0];
        #pragma unroll
        for (int j=1;j<12;j++) mx = fmaxf(mx, vm_s[bt][j]);
        float e[12], ssum = 0.f;
        #pragma unroll
        for (int j=0;j<12;j++){ e[j] = __expf(vm_s[bt][j]-mx); ssum += e[j]; }
        float inv = 1.0f/ssum;
        #pragma unroll
        for (int j=0;j<12;j++) vs_s[bt][j] = e[j]*inv;
    }
    __syncthreads();

    // ---- u[bt][i] = sum_l vs[bt][l] * w41[i,l] -----------------------------
    if (tid < BT*FR_){
        int bt = tid / FR_, i = tid % FR_;
        float u = 0.f;
        #pragma unroll
        for (int l=0;l<12;l++) u = fmaf(vs_s[bt][l], w41[i*12+l], u);
        u_s[bt][i] = u;
    }
    __syncthreads();

    // ---- per-batch: p[c], d[c], reductions, then g_pp / g_an ---------------
    float Vd = 0.f;
    for (int bt=0;bt<BT;bt++){
        float p = 0.f, d = 0.f;
        if (tid < C_){
            #pragma unroll
            for (int i=0;i<6;i++){
                float wv = w42[tid*6+i];
                p = fmaf(u_s[bt][i], wv, p);
                d = fmaf(b41[i],     wv, d);
            }
            d += b42[tid];
        }
        float s0 = p, s1 = p*p, s2 = p*d, s3 = d, s4 = d*d;
        #pragma unroll
        for (int o=16;o>0;o>>=1){
            s0 += __shfl_down_sync(0xffffffffu, s0, o);
            s1 += __shfl_down_sync(0xffffffffu, s1, o);
            s2 += __shfl_down_sync(0xffffffffu, s2, o);
            s3 += __shfl_down_sync(0xffffffffu, s3, o);
            s4 += __shfl_down_sync(0xffffffffu, s4, o);
        }
        int wid = tid >> 5;
        if ((tid & 31) == 0){
            wred[wid][0]=s0; wred[wid][1]=s1; wred[wid][2]=s2; wred[wid][3]=s3; wred[wid][4]=s4;
        }
        __syncthreads();
        if (tid == 0){
            float t0=0,t1=0,t2=0,t3=0,t4=0;
            #pragma unroll
            for (int w=0;w<8;w++){ t0+=wred[w][0]; t1+=wred[w][1]; t2+=wred[w][2]; t3+=wred[w][3]; t4+=wred[w][4]; }
            tot[0]=t0; tot[1]=t1; tot[2]=t2; tot[3]=t3; tot[4]=t4;
            if (bt == 0){
                float mdd = t3*(1.0f/C_);
                sh_Vd = t4*(1.0f/C_) - mdd*mdd;
            }
        }
        __syncthreads();
        if (bt == 0) Vd = sh_Vd;
        float mp  = tot[0]*(1.0f/C_);
        float md  = tot[3]*(1.0f/C_);
        float Vp  = tot[1]*(1.0f/C_) - mp*mp;
        float Cpd = tot[2]*(1.0f/C_) - mp*md;
        if (tid < C_){
            g_pp[(b0+bt)*C_ + tid] = p - mp;
            if (bt == 0 && blockIdx.x == 0){
                float g = ln_g[tid];
                g_ctab[tid] = make_float4(g, (d - md)*g, ln_b[tid], 0.f);
            }
        }
        if (tid < HW_){
            float a   = kqs_s[bt][tid];
            float var = fmaf(a, fmaf(a, Vp, 2.0f*Cpd), Vd) + 1e-5f;
            float rs  = rsqrtf(var);
            g_an[(b0+bt)*HW_ + tid] = make_float2(a*rs, rs);
        }
        __syncthreads();
    }
}

// ============================================================================
// K2: 2048 blocks = (batch) x (c-half). Thread-per-n, 100 channels per block
// in groups of 10 (10 outstanding LDGs). out = x/(1+exp(-relu(...))).
// ============================================================================
__global__ __launch_bounds__(256, 8) void k2_kernel(
    const float* __restrict__ X, float* __restrict__ out)
{
    __shared__ float4 cdat[100];         // {pp*g, (d-md)*g, ln_b, 0}

    const int tid = threadIdx.x;
    const int b   = blockIdx.x >> 1;
    const int c0  = (blockIdx.x & 1) * 100;

    if (tid < 100){
        int c = c0 + tid;
        float  pp = g_pp[b*C_ + c];
        float4 ct = g_ctab[c];
        cdat[tid] = make_float4(pp*ct.x, ct.y, ct.z, 0.f);
    }
    __syncthreads();

    if (tid < HW_){
        float2 an = g_an[b*HW_ + tid];
        const float* xp = X   + (size_t)b*NELEM + c0*HW_ + tid;
        float*       op = out + (size_t)b*NELEM + c0*HW_ + tid;
        #pragma unroll 1
        for (int cg=0; cg<100; cg+=10){
            float xv[10];
            #pragma unroll
            for (int e=0;e<10;e++) xv[e] = xp[e*HW_];    // 10 outstanding LDGs
            #pragma unroll
            for (int e=0;e<10;e++){
                float4 cd = cdat[cg+e];
                float t = fmaf(an.x, cd.x, fmaf(an.y, cd.y, cd.z));
                t = fmaxf(t, 0.f);
                float ex = __expf(-t);
                op[e*HW_] = __fdividef(xv[e], 1.0f + ex);
            }
            xp += 10*HW_; op += 10*HW_;
        }
    }
}

// ============================================================================
extern "C" void kernel_launch(void* const* d_in, const int* in_sizes, int n_in,
                              void* d_out, int out_size)
{
    const float* X    = (const float*)d_in[0];
    const float* w11  = (const float*)d_in[1];
    const float* b11  = (const float*)d_in[2];
    const float* w21  = (const float*)d_in[3];
    const float* b21  = (const float*)d_in[4];
    const float* w31  = (const float*)d_in[5];
    const float* b31  = (const float*)d_in[6];
    const float* w41  = (const float*)d_in[7];
    const float* b41  = (const float*)d_in[8];
    const float* w42  = (const float*)d_in[9];
    const float* b42  = (const float*)d_in[10];
    const float* ln_g = (const float*)d_in[11];
    const float* ln_b = (const float*)d_in[12];
    float* out = (float*)d_out;

    cudaFuncSetAttribute(k1_kernel, cudaFuncAttributeMaxDynamicSharedMemorySize, SM_TOTAL);

    k1_kernel<<<B_/BT, 256, SM_TOTAL>>>(X, w11,b11, w21,b21, w31,b31,
                                        w41,b41, w42,b42, ln_g, ln_b);
    k2_kernel<<<B_*2, 256>>>(X, out);
}